// round 14
// baseline (speedup 1.0000x reference)
#include <cuda_runtime.h>
#include <cuda_fp16.h>
#include <cstdint>
#include <cstddef>

// Problem shape (fixed by the dataset): B=8192, T=16, C=512, H=8, DH=64
#define BT_TOTAL 131072          // B*T
#define C_DIM    512

// ---------------------------------------------------------------------------
// Scratch (device globals; no allocations allowed). All fp16.
// ---------------------------------------------------------------------------
__device__ __half g_xh[BT_TOTAL * C_DIM];    // x converted to fp16
__device__ __half g_wq[C_DIM * C_DIM];
__device__ __half g_wk[C_DIM * C_DIM];
__device__ __half g_wv[C_DIM * C_DIM];
__device__ __half g_wo[C_DIM * C_DIM];
__device__ __half g_q[BT_TOTAL * C_DIM];
__device__ __half g_k[BT_TOTAL * C_DIM];
__device__ __half g_v[BT_TOTAL * C_DIM];
__device__ __half g_ctx[BT_TOTAL * C_DIM];

// ---------------------------------------------------------------------------
// Helpers
// ---------------------------------------------------------------------------
__device__ __forceinline__ uint32_t smem_u32(const void* p) {
    uint32_t a;
    asm("{ .reg .u64 t; cvta.to.shared.u64 t, %1; cvt.u32.u64 %0, t; }" : "=r"(a) : "l"(p));
    return a;
}
__device__ __forceinline__ uint32_t h2b(__half2 h) {
    return *reinterpret_cast<uint32_t*>(&h);
}
__device__ __forceinline__ void mma_f16(float* d, const uint32_t* a, const uint32_t* b) {
    asm volatile(
        "mma.sync.aligned.m16n8k16.row.col.f32.f16.f16.f32 "
        "{%0,%1,%2,%3}, {%4,%5,%6,%7}, {%8,%9}, {%0,%1,%2,%3};\n"
        : "+f"(d[0]), "+f"(d[1]), "+f"(d[2]), "+f"(d[3])
        : "r"(a[0]), "r"(a[1]), "r"(a[2]), "r"(a[3]),
          "r"(b[0]), "r"(b[1]));
}
#define LDSM4(r0, r1, r2, r3, addr)                                            \
    asm volatile("ldmatrix.sync.aligned.m8n8.x4.shared.b16 {%0,%1,%2,%3}, [%4];" \
        : "=r"(r0), "=r"(r1), "=r"(r2), "=r"(r3) : "r"(addr))
#define CP_ASYNC16(dst, src)                                                   \
    asm volatile("cp.async.cg.shared.global [%0], [%1], 16;" :: "r"(dst), "l"(src))
#define CP_COMMIT()  asm volatile("cp.async.commit_group;" ::: "memory")
#define CP_WAIT(n)   asm volatile("cp.async.wait_group %0;" :: "n"(n) : "memory")

// ---------------------------------------------------------------------------
// fp32 -> fp16 bulk convert (4 floats per thread)
// ---------------------------------------------------------------------------
__global__ __launch_bounds__(256)
void cvt_kernel(const float4* __restrict__ src, uint2* __restrict__ dst, int n4) {
    int i = blockIdx.x * 256 + threadIdx.x;
    if (i < n4) {
        float4 v = src[i];
        dst[i] = make_uint2(h2b(__floats2half2_rn(v.x, v.y)),
                            h2b(__floats2half2_rn(v.z, v.w)));
    }
}

// ===========================================================================
// fp16 GEMM core: tile 256(M) x 128(N) x 32(K), 512 threads (16 warps, 4x4
// warp grid, warp tile 64x32 — per-warp compute identical to the proven R11
// kernel). 3-stage cp.async ring, TWO barriers per kt (R12 lesson: the
// trailing barrier is a load-bearing rate limiter).
// 25% fewer LDGSTS per MAC than the 128x128 tile (LSU-issue-bound).
// smem: stage s: A @ s*30720 (256 rows x 80B), B @ s*30720+20480 (128 x 80B).
// Total 92160 B -> 1 CTA x 512 thr / SM (same 16 warps as 2x256).
// ===========================================================================
#define GEMM_CORE_DECLS                                                        \
    extern __shared__ char smraw[];                                            \
    const uint32_t sbase = smem_u32(smraw);                                    \
    const int tid   = threadIdx.x;                                             \
    const int lane  = tid & 31;                                                \
    const int warp  = tid >> 5;                                                \
    const int warpM = warp >> 2;                                               \
    const int warpN = warp & 3;                                                \
    const int gid   = lane >> 2;                                               \
    const int tig   = lane & 3;                                                \
    const uint32_t aOff = (uint32_t)((warpM * 64 + (lane & 15)) * 80 + (lane >> 4) * 16); \
    const uint32_t bOff = (uint32_t)((warpN * 32 + (lane >> 4) * 8 + (lane & 7)) * 80     \
                                     + ((lane >> 3) & 1) * 16);                \
    float acc[4][4][4];                                                        \
    _Pragma("unroll")                                                          \
    for (int i = 0; i < 4; ++i)                                                \
        _Pragma("unroll")                                                      \
        for (int j = 0; j < 4; ++j)                                            \
            _Pragma("unroll")                                                  \
            for (int r = 0; r < 4; ++r) acc[i][j][r] = 0.f;

#define GEMM_ISSUE(kt)                                                         \
    {                                                                          \
        const int s_ = (kt) % 3;                                               \
        const uint32_t da_ = sbase + s_ * 30720;                               \
        const uint32_t db_ = sbase + s_ * 30720 + 20480;                       \
        const __half* ag_ = Ag + (kt) * 32;                                    \
        const __half* bg_ = Bg + (kt) * 32;                                    \
        _Pragma("unroll")                                                      \
        for (int i_ = 0; i_ < 2; ++i_) {                                       \
            const int idx_ = tid + i_ * 512;                                   \
            const int row_ = idx_ >> 2, c_ = idx_ & 3;                         \
            CP_ASYNC16(da_ + (uint32_t)(row_ * 80 + c_ * 16),                  \
                       ag_ + (size_t)row_ * 512 + c_ * 8);                     \
        }                                                                      \
        {                                                                      \
            const int row_ = tid >> 2, c_ = tid & 3;                           \
            CP_ASYNC16(db_ + (uint32_t)(row_ * 80 + c_ * 16),                  \
                       bg_ + (size_t)row_ * 512 + c_ * 8);                     \
        }                                                                      \
        CP_COMMIT();                                                           \
    }

#define GEMM_COMPUTE(s)                                                        \
    {                                                                          \
        const uint32_t sa_ = sbase + (s) * 30720 + aOff;                       \
        const uint32_t sb_ = sbase + (s) * 30720 + 20480 + bOff;               \
        _Pragma("unroll")                                                      \
        for (int ks = 0; ks < 2; ++ks) {                                       \
            uint32_t aF[4][4], bF[8];                                          \
            _Pragma("unroll")                                                  \
            for (int mt = 0; mt < 4; ++mt)                                     \
                LDSM4(aF[mt][0], aF[mt][1], aF[mt][2], aF[mt][3],              \
                      sa_ + mt * 1280 + ks * 32);                              \
            _Pragma("unroll")                                                  \
            for (int p = 0; p < 2; ++p)                                        \
                LDSM4(bF[p*4], bF[p*4+1], bF[p*4+2], bF[p*4+3],                \
                      sb_ + p * 1280 + ks * 32);                               \
            _Pragma("unroll")                                                  \
            for (int mt = 0; mt < 4; ++mt)                                     \
                _Pragma("unroll")                                              \
                for (int nt = 0; nt < 4; ++nt)                                 \
                    mma_f16(acc[mt][nt], aF[mt], &bF[nt * 2]);                 \
        }                                                                      \
    }

#define GEMM_MAINLOOP                                                          \
    GEMM_ISSUE(0)                                                              \
    GEMM_ISSUE(1)                                                              \
    _Pragma("unroll 1")                                                        \
    for (int kt = 0; kt < 16; ++kt) {                                          \
        if (kt + 2 < 16) { GEMM_ISSUE(kt + 2) } else { CP_COMMIT(); }          \
        CP_WAIT(2);                                                            \
        __syncthreads();                                                       \
        GEMM_COMPUTE(kt % 3)                                                   \
        __syncthreads();                                                       \
    }

// ---------------------------------------------------------------------------
// Merged QKV GEMM: grid (12, M/256). blockIdx.x>>2 selects {q,k,v}.
// ---------------------------------------------------------------------------
__global__ __launch_bounds__(512, 1)
void gemm_qkv_kernel(const __half* __restrict__ A,
                     __half* __restrict__ Oq, __half* __restrict__ Ok,
                     __half* __restrict__ Ov) {
    GEMM_CORE_DECLS
    const int sel = blockIdx.x >> 2;
    const int bn  = blockIdx.x & 3;
    const int bm  = blockIdx.y;

    const __half* Bw = (sel == 0) ? g_wq : (sel == 1) ? g_wk : g_wv;
    __half*       Co = (sel == 0) ? Oq   : (sel == 1) ? Ok   : Ov;

    const __half* Ag = A  + (size_t)bm * 256 * 512;
    const __half* Bg = Bw + (size_t)bn * 128 * 512;

    GEMM_MAINLOOP

    const size_t cbase = (size_t)bm * 256 * 512 + (size_t)bn * 128;
    #pragma unroll
    for (int mt = 0; mt < 4; ++mt) {
        const int r0 = warpM * 64 + mt * 16 + gid;
        #pragma unroll
        for (int nt = 0; nt < 4; ++nt) {
            const int c0 = warpN * 32 + nt * 8 + tig * 2;
            size_t o = cbase + (size_t)r0 * 512 + c0;
            *(__half2*)(Co + o)           = __floats2half2_rn(acc[mt][nt][0], acc[mt][nt][1]);
            *(__half2*)(Co + o + 8 * 512) = __floats2half2_rn(acc[mt][nt][2], acc[mt][nt][3]);
        }
    }
}

// ---------------------------------------------------------------------------
// Output GEMM: A = g_ctx fp16, B = g_wo fp16, C = out fp32 + bias.
// ---------------------------------------------------------------------------
__global__ __launch_bounds__(512, 1)
void gemm_out_kernel(const __half* __restrict__ A, float* __restrict__ Cout,
                     const float* __restrict__ bias) {
    GEMM_CORE_DECLS
    const int bn = blockIdx.x;
    const int bm = blockIdx.y;

    const __half* Ag = A    + (size_t)bm * 256 * 512;
    const __half* Bg = g_wo + (size_t)bn * 128 * 512;

    GEMM_MAINLOOP

    const size_t cbase = (size_t)bm * 256 * 512 + (size_t)bn * 128;
    #pragma unroll
    for (int mt = 0; mt < 4; ++mt) {
        const int r0 = warpM * 64 + mt * 16 + gid;
        #pragma unroll
        for (int nt = 0; nt < 4; ++nt) {
            const int c0 = warpN * 32 + nt * 8 + tig * 2;
            const float b0 = bias[bn * 128 + c0];
            const float b1 = bias[bn * 128 + c0 + 1];
            size_t o = cbase + (size_t)r0 * 512 + c0;
            *(float2*)(Cout + o)           = make_float2(acc[mt][nt][0] + b0, acc[mt][nt][1] + b1);
            *(float2*)(Cout + o + 8 * 512) = make_float2(acc[mt][nt][2] + b0, acc[mt][nt][3] + b1);
        }
    }
}

// ---------------------------------------------------------------------------
// Fused attention middle (EXACT R11 config — measured best: occ 3, separate
// sSim buffer; R13's alias+occ4 variant was +16us).
// ---------------------------------------------------------------------------
__global__ __launch_bounds__(256, 3)
void attn_kernel(const float* __restrict__ mask,
                 const float* __restrict__ ln_g, const float* __restrict__ ln_b,
                 const float* __restrict__ beta) {
    constexpr int PADH = 520;   // fp16 row stride (halves)
    extern __shared__ char smraw[];
    float*  sSym = (float*)(smraw);                  // 256 f
    float*  sSim = (float*)(smraw + 1024);           // 2048 f
    __half* sQh  = (__half*)(smraw + 9216);          // 16*520 h
    __half* sKh  = (__half*)(smraw + 25856);         // 16*520 h
    __half* sMh  = (__half*)(smraw + 42496);         // 16*520 h (end 59136)

    const int tid  = threadIdx.x;
    const int warp = tid >> 5;
    const int lane = tid & 31;
    const int gid  = lane >> 2;
    const int tig  = lane & 3;
    const size_t base = (size_t)blockIdx.x * 8192;

    // async prefetch q,k (fp16) -> smem; overlaps LN + sym
    {
        const uint32_t sqb = smem_u32(sQh);
        const uint32_t skb = smem_u32(sKh);
        const __half* qg = g_q + base;
        const __half* kg = g_k + base;
        #pragma unroll
        for (int r = 0; r < 4; ++r) {
            int f = tid + 256 * r;
            int row = f >> 6, c8 = f & 63;
            uint32_t off = (uint32_t)(row * PADH + c8 * 8) * 2u;
            asm volatile("cp.async.ca.shared.global [%0], [%1], 16;"
                         :: "r"(sqb + off), "l"(qg + (size_t)row * 512 + c8 * 8));
            asm volatile("cp.async.ca.shared.global [%0], [%1], 16;"
                         :: "r"(skb + off), "l"(kg + (size_t)row * 512 + c8 * 8));
        }
        CP_COMMIT();
    }

    // layernorm(mask) -> sMh (fp16): warp per row, 2 rows/warp
    #pragma unroll
    for (int p = 0; p < 2; ++p) {
        const int r = warp + p * 8;
        const float4* mg = (const float4*)(mask + base + (size_t)r * 512);
        float4 vv[4];
        float s = 0.f, sq = 0.f;
        #pragma unroll
        for (int u = 0; u < 4; ++u) {
            vv[u] = mg[lane + 32 * u];
            s  += vv[u].x + vv[u].y + vv[u].z + vv[u].w;
            sq += vv[u].x * vv[u].x + vv[u].y * vv[u].y + vv[u].z * vv[u].z + vv[u].w * vv[u].w;
        }
        #pragma unroll
        for (int o = 16; o; o >>= 1) {
            s  += __shfl_xor_sync(0xffffffffu, s,  o);
            sq += __shfl_xor_sync(0xffffffffu, sq, o);
        }
        const float mu  = s * (1.f / 512.f);
        const float inv = rsqrtf(sq * (1.f / 512.f) - mu * mu + 1e-5f);
        const float4* gg = (const float4*)ln_g;
        const float4* bv = (const float4*)ln_b;
        uint2* mr = (uint2*)(sMh + r * PADH);
        #pragma unroll
        for (int u = 0; u < 4; ++u) {
            float4 g4 = gg[lane + 32 * u], b4 = bv[lane + 32 * u];
            float m0 = (vv[u].x - mu) * inv * g4.x + b4.x;
            float m1 = (vv[u].y - mu) * inv * g4.y + b4.y;
            float m2 = (vv[u].z - mu) * inv * g4.z + b4.z;
            float m3 = (vv[u].w - mu) * inv * g4.w + b4.w;
            mr[lane + 32 * u] = make_uint2(h2b(__floats2half2_rn(m0, m1)),
                                           h2b(__floats2half2_rn(m2, m3)));
        }
    }
    __syncthreads();

    // sym = (m m^T)/sqrt(C) via fp16 mma: warps 0,1
    if (warp < 2) {
        float acc4[4] = {0.f, 0.f, 0.f, 0.f};
        const int nb = warp * 8;
        #pragma unroll 4
        for (int k16 = 0; k16 < 32; ++k16) {
            const int kb = k16 * 16 + tig * 2;
            uint32_t aF[4], bF[2];
            aF[0] = *(const uint32_t*)(sMh + gid * PADH + kb);
            aF[1] = *(const uint32_t*)(sMh + (gid + 8) * PADH + kb);
            aF[2] = *(const uint32_t*)(sMh + gid * PADH + kb + 8);
            aF[3] = *(const uint32_t*)(sMh + (gid + 8) * PADH + kb + 8);
            bF[0] = *(const uint32_t*)(sMh + (nb + gid) * PADH + kb);
            bF[1] = *(const uint32_t*)(sMh + (nb + gid) * PADH + kb + 8);
            mma_f16(acc4, aF, bF);
        }
        const float S = 0.044194173824159216f;  // 1/sqrt(512)
        const int cc = nb + tig * 2;
        sSym[gid * 16 + cc]           = (gid == cc)         ? 0.f : acc4[0] * S;
        sSym[gid * 16 + cc + 1]       = (gid == cc + 1)     ? 0.f : acc4[1] * S;
        sSym[(gid + 8) * 16 + cc]     = (gid + 8 == cc)     ? 0.f : acc4[2] * S;
        sSym[(gid + 8) * 16 + cc + 1] = (gid + 8 == cc + 1) ? 0.f : acc4[3] * S;
    }
    asm volatile("cp.async.wait_group 0;" ::: "memory");
    __syncthreads();

    // sim[h] = q_h k_h^T /8 + sym*beta[h] via fp16 mma: warp h
    {
        const int hb = warp * 64;
        const float bh = beta[warp];
        float acc8[2][4];
        #pragma unroll
        for (int nt = 0; nt < 2; ++nt)
            #pragma unroll
            for (int r = 0; r < 4; ++r) acc8[nt][r] = 0.f;

        #pragma unroll
        for (int k16 = 0; k16 < 4; ++k16) {
            const int kb = hb + k16 * 16 + tig * 2;
            uint32_t aF[4], bF[2];
            aF[0] = *(const uint32_t*)(sQh + gid * PADH + kb);
            aF[1] = *(const uint32_t*)(sQh + (gid + 8) * PADH + kb);
            aF[2] = *(const uint32_t*)(sQh + gid * PADH + kb + 8);
            aF[3] = *(const uint32_t*)(sQh + (gid + 8) * PADH + kb + 8);
            #pragma unroll
            for (int nt = 0; nt < 2; ++nt) {
                bF[0] = *(const uint32_t*)(sKh + (nt * 8 + gid) * PADH + kb);
                bF[1] = *(const uint32_t*)(sKh + (nt * 8 + gid) * PADH + kb + 8);
                mma_f16(acc8[nt], aF, bF);
            }
        }
        float* simh = sSim + warp * 256;
        #pragma unroll
        for (int nt = 0; nt < 2; ++nt) {
            const int c0 = nt * 8 + tig * 2;
            simh[gid * 16 + c0]           = acc8[nt][0] * 0.125f + sSym[gid * 16 + c0] * bh;
            simh[gid * 16 + c0 + 1]       = acc8[nt][1] * 0.125f + sSym[gid * 16 + c0 + 1] * bh;
            simh[(gid + 8) * 16 + c0]     = acc8[nt][2] * 0.125f + sSym[(gid + 8) * 16 + c0] * bh;
            simh[(gid + 8) * 16 + c0 + 1] = acc8[nt][3] * 0.125f + sSym[(gid + 8) * 16 + c0 + 1] * bh;
        }
    }
    __syncthreads();

    // softmax over j: one thread per (h,i) row
    if (tid < 128) {
        float* row = sSim + tid * 16;
        float mx = row[0];
        #pragma unroll
        for (int j = 1; j < 16; ++j) mx = fmaxf(mx, row[j]);
        float s = 0.f;
        #pragma unroll
        for (int j = 0; j < 16; ++j) { float e = __expf(row[j] - mx); row[j] = e; s += e; }
        const float inv = 1.f / s;
        #pragma unroll
        for (int j = 0; j < 16; ++j) row[j] *= inv;
    }
    __syncthreads();

    // ctx = attn @ v : thread owns 2 adjacent cols
    {
        const __half2* vg2 = (const __half2*)(g_v + base);
        float2 vr[16];
        #pragma unroll
        for (int j = 0; j < 16; ++j) vr[j] = __half22float2(vg2[j * 256 + tid]);
        const float* ab = sSim + warp * 256;
        __half2* cg2 = (__half2*)(g_ctx + base);
        #pragma unroll
        for (int i = 0; i < 16; ++i) {
            const float* ar = ab + i * 16;
            float a0 = 0.f, a1 = 0.f;
            #pragma unroll
            for (int j = 0; j < 16; ++j) {
                const float a = ar[j];
                a0 += a * vr[j].x;
                a1 += a * vr[j].y;
            }
            cg2[i * 256 + tid] = __floats2half2_rn(a0, a1);
        }
    }
}

// ---------------------------------------------------------------------------
// Launch
// ---------------------------------------------------------------------------
extern "C" void kernel_launch(void* const* d_in, const int* in_sizes, int n_in,
                              void* d_out, int out_size) {
    const float* x    = (const float*)d_in[0];
    const float* mask = (const float*)d_in[1];
    const float* w_q  = (const float*)d_in[2];
    const float* w_k  = (const float*)d_in[3];
    const float* w_v  = (const float*)d_in[4];
    const float* w_o  = (const float*)d_in[5];
    const float* b_o  = (const float*)d_in[6];
    const float* beta = (const float*)d_in[7];
    const float* ln_g = (const float*)d_in[8];
    const float* ln_b = (const float*)d_in[9];
    float* out = (float*)d_out;

    __half *xh, *wq, *wk, *wv, *wo, *q, *k, *v, *ctx;
    cudaGetSymbolAddress((void**)&xh,  g_xh);
    cudaGetSymbolAddress((void**)&wq,  g_wq);
    cudaGetSymbolAddress((void**)&wk,  g_wk);
    cudaGetSymbolAddress((void**)&wv,  g_wv);
    cudaGetSymbolAddress((void**)&wo,  g_wo);
    cudaGetSymbolAddress((void**)&q,   g_q);
    cudaGetSymbolAddress((void**)&k,   g_k);
    cudaGetSymbolAddress((void**)&v,   g_v);
    cudaGetSymbolAddress((void**)&ctx, g_ctx);

    const int bt = in_sizes[0] / C_DIM;       // B*T = 131072
    const int bb = bt / 16;                   // B   = 8192

    const int gemm_smem = 92160;
    const int attn_smem = 59136;
    cudaFuncSetAttribute(gemm_qkv_kernel, cudaFuncAttributeMaxDynamicSharedMemorySize, gemm_smem);
    cudaFuncSetAttribute(gemm_out_kernel, cudaFuncAttributeMaxDynamicSharedMemorySize, gemm_smem);
    cudaFuncSetAttribute(attn_kernel,     cudaFuncAttributeMaxDynamicSharedMemorySize, attn_smem);

    // fp32 -> fp16 converts (x + 4 weight matrices)
    const int n4x = bt * 128;                 // x float4 count
    cvt_kernel<<<(n4x + 255) / 256, 256>>>((const float4*)x,   (uint2*)xh, n4x);
    cvt_kernel<<<256, 256>>>((const float4*)w_q, (uint2*)wq, 65536);
    cvt_kernel<<<256, 256>>>((const float4*)w_k, (uint2*)wk, 65536);
    cvt_kernel<<<256, 256>>>((const float4*)w_v, (uint2*)wv, 65536);
    cvt_kernel<<<256, 256>>>((const float4*)w_o, (uint2*)wo, 65536);

    dim3 grid_qkv(12, bt / 256);              // 3 outputs x 4 N-tiles, M/256
    dim3 grid_out(4,  bt / 256);
    gemm_qkv_kernel<<<grid_qkv, 512, gemm_smem>>>(xh, q, k, v);
    attn_kernel<<<bb, 256, attn_smem>>>(mask, ln_g, ln_b, beta);
    gemm_out_kernel<<<grid_out, 512, gemm_smem>>>(ctx, out, b_o);
}

// round 15
// speedup vs baseline: 1.1903x; 1.1903x over previous
#include <cuda_runtime.h>
#include <cuda_fp16.h>
#include <cstdint>
#include <cstddef>

// Problem shape (fixed by the dataset): B=8192, T=16, C=512, H=8, DH=64
#define BT_TOTAL 131072          // B*T
#define C_DIM    512

// ---------------------------------------------------------------------------
// Scratch (device globals; no allocations allowed). All fp16.
// ---------------------------------------------------------------------------
__device__ __half g_xh[BT_TOTAL * C_DIM];    // x converted to fp16
__device__ __half g_wq[C_DIM * C_DIM];
__device__ __half g_wk[C_DIM * C_DIM];
__device__ __half g_wv[C_DIM * C_DIM];
__device__ __half g_wo[C_DIM * C_DIM];
__device__ __half g_q[BT_TOTAL * C_DIM];
__device__ __half g_k[BT_TOTAL * C_DIM];
__device__ __half g_v[BT_TOTAL * C_DIM];
__device__ __half g_ctx[BT_TOTAL * C_DIM];

// ---------------------------------------------------------------------------
// Helpers
// ---------------------------------------------------------------------------
__device__ __forceinline__ uint32_t smem_u32(const void* p) {
    uint32_t a;
    asm("{ .reg .u64 t; cvta.to.shared.u64 t, %1; cvt.u32.u64 %0, t; }" : "=r"(a) : "l"(p));
    return a;
}
__device__ __forceinline__ uint32_t h2b(__half2 h) {
    return *reinterpret_cast<uint32_t*>(&h);
}
__device__ __forceinline__ void mma_f16(float* d, const uint32_t* a, const uint32_t* b) {
    asm volatile(
        "mma.sync.aligned.m16n8k16.row.col.f32.f16.f16.f32 "
        "{%0,%1,%2,%3}, {%4,%5,%6,%7}, {%8,%9}, {%0,%1,%2,%3};\n"
        : "+f"(d[0]), "+f"(d[1]), "+f"(d[2]), "+f"(d[3])
        : "r"(a[0]), "r"(a[1]), "r"(a[2]), "r"(a[3]),
          "r"(b[0]), "r"(b[1]));
}
#define LDSM4(r0, r1, r2, r3, addr)                                            \
    asm volatile("ldmatrix.sync.aligned.m8n8.x4.shared.b16 {%0,%1,%2,%3}, [%4];" \
        : "=r"(r0), "=r"(r1), "=r"(r2), "=r"(r3) : "r"(addr))
#define CP_ASYNC16(dst, src)                                                   \
    asm volatile("cp.async.cg.shared.global [%0], [%1], 16;" :: "r"(dst), "l"(src))
#define CP_COMMIT()  asm volatile("cp.async.commit_group;" ::: "memory")
#define CP_WAIT(n)   asm volatile("cp.async.wait_group %0;" :: "n"(n) : "memory")

// ---------------------------------------------------------------------------
// fp32 -> fp16 bulk convert: x (big, own launch)
// ---------------------------------------------------------------------------
__global__ __launch_bounds__(256)
void cvt_kernel(const float4* __restrict__ src, uint2* __restrict__ dst, int n4) {
    int i = blockIdx.x * 256 + threadIdx.x;
    if (i < n4) {
        float4 v = src[i];
        dst[i] = make_uint2(h2b(__floats2half2_rn(v.x, v.y)),
                            h2b(__floats2half2_rn(v.z, v.w)));
    }
}

// All 4 weight matrices in ONE launch (grid 1024; 256 blocks per matrix).
__global__ __launch_bounds__(256)
void cvt4_kernel(const float4* __restrict__ s0, const float4* __restrict__ s1,
                 const float4* __restrict__ s2, const float4* __restrict__ s3,
                 uint2* __restrict__ d0, uint2* __restrict__ d1,
                 uint2* __restrict__ d2, uint2* __restrict__ d3) {
    const int m = blockIdx.x >> 8;                    // 0..3
    const int i = (blockIdx.x & 255) * 256 + threadIdx.x;  // 0..65535
    const float4* s = (m == 0) ? s0 : (m == 1) ? s1 : (m == 2) ? s2 : s3;
    uint2*       d = (m == 0) ? d0 : (m == 1) ? d1 : (m == 2) ? d2 : d3;
    float4 v = s[i];
    d[i] = make_uint2(h2b(__floats2half2_rn(v.x, v.y)),
                      h2b(__floats2half2_rn(v.z, v.w)));
}

// ===========================================================================
// fp16 GEMM core (EXACT R11 — measured best. 3-stage ring, TWO barriers per
// kt. R12 removed the trailing barrier: +490us (warp-skew L1tex contention).
// R14 grew the tile to 256x128 @ 1 CTA/SM: +200us (no co-resident CTA to
// cover barrier drains). This configuration is a verified local optimum.)
// smem: A stages @ s*10240, B stages @ 30720 + s*10240. Total 61440 B.
// ===========================================================================
#define GEMM_CORE_DECLS                                                        \
    extern __shared__ char smraw[];                                            \
    const uint32_t sbase = smem_u32(smraw);                                    \
    const int tid   = threadIdx.x;                                             \
    const int lane  = tid & 31;                                                \
    const int warp  = tid >> 5;                                                \
    const int warpM = warp >> 2;                                               \
    const int warpN = warp & 3;                                                \
    const int gid   = lane >> 2;                                               \
    const int tig   = lane & 3;                                                \
    const uint32_t aOff = (uint32_t)((warpM * 64 + (lane & 15)) * 80 + (lane >> 4) * 16); \
    const uint32_t bOff = (uint32_t)((warpN * 32 + (lane >> 4) * 8 + (lane & 7)) * 80     \
                                     + ((lane >> 3) & 1) * 16);                \
    float acc[4][4][4];                                                        \
    _Pragma("unroll")                                                          \
    for (int i = 0; i < 4; ++i)                                                \
        _Pragma("unroll")                                                      \
        for (int j = 0; j < 4; ++j)                                            \
            _Pragma("unroll")                                                  \
            for (int r = 0; r < 4; ++r) acc[i][j][r] = 0.f;

#define GEMM_ISSUE(kt)                                                         \
    {                                                                          \
        const int s_ = (kt) % 3;                                               \
        const uint32_t da_ = sbase + s_ * 10240;                               \
        const uint32_t db_ = sbase + 30720 + s_ * 10240;                       \
        const __half* ag_ = Ag + (kt) * 32;                                    \
        const __half* bg_ = Bg + (kt) * 32;                                    \
        _Pragma("unroll")                                                      \
        for (int i_ = 0; i_ < 2; ++i_) {                                       \
            const int idx_ = tid + i_ * 256;                                   \
            const int row_ = idx_ >> 2, c_ = idx_ & 3;                         \
            CP_ASYNC16(da_ + (uint32_t)(row_ * 80 + c_ * 16),                  \
                       ag_ + (size_t)row_ * 512 + c_ * 8);                     \
            CP_ASYNC16(db_ + (uint32_t)(row_ * 80 + c_ * 16),                  \
                       bg_ + (size_t)row_ * 512 + c_ * 8);                     \
        }                                                                      \
        CP_COMMIT();                                                           \
    }

#define GEMM_COMPUTE(s)                                                        \
    {                                                                          \
        const uint32_t sa_ = sbase + (s) * 10240 + aOff;                       \
        const uint32_t sb_ = sbase + 30720 + (s) * 10240 + bOff;               \
        _Pragma("unroll")                                                      \
        for (int ks = 0; ks < 2; ++ks) {                                       \
            uint32_t aF[4][4], bF[8];                                          \
            _Pragma("unroll")                                                  \
            for (int mt = 0; mt < 4; ++mt)                                     \
                LDSM4(aF[mt][0], aF[mt][1], aF[mt][2], aF[mt][3],              \
                      sa_ + mt * 1280 + ks * 32);                              \
            _Pragma("unroll")                                                  \
            for (int p = 0; p < 2; ++p)                                        \
                LDSM4(bF[p*4], bF[p*4+1], bF[p*4+2], bF[p*4+3],                \
                      sb_ + p * 1280 + ks * 32);                               \
            _Pragma("unroll")                                                  \
            for (int mt = 0; mt < 4; ++mt)                                     \
                _Pragma("unroll")                                              \
                for (int nt = 0; nt < 4; ++nt)                                 \
                    mma_f16(acc[mt][nt], aF[mt], &bF[nt * 2]);                 \
        }                                                                      \
    }

#define GEMM_MAINLOOP                                                          \
    GEMM_ISSUE(0)                                                              \
    GEMM_ISSUE(1)                                                              \
    _Pragma("unroll 1")                                                        \
    for (int kt = 0; kt < 16; ++kt) {                                          \
        if (kt + 2 < 16) { GEMM_ISSUE(kt + 2) } else { CP_COMMIT(); }          \
        CP_WAIT(2);                                                            \
        __syncthreads();                                                       \
        GEMM_COMPUTE(kt % 3)                                                   \
        __syncthreads();                                                       \
    }

// ---------------------------------------------------------------------------
// Merged QKV GEMM: grid (12, M/128). blockIdx.x>>2 selects {q,k,v}.
// ---------------------------------------------------------------------------
__global__ __launch_bounds__(256, 2)
void gemm_qkv_kernel(const __half* __restrict__ A,
                     __half* __restrict__ Oq, __half* __restrict__ Ok,
                     __half* __restrict__ Ov) {
    GEMM_CORE_DECLS
    const int sel = blockIdx.x >> 2;
    const int bn  = blockIdx.x & 3;
    const int bm  = blockIdx.y;

    const __half* Bw = (sel == 0) ? g_wq : (sel == 1) ? g_wk : g_wv;
    __half*       Co = (sel == 0) ? Oq   : (sel == 1) ? Ok   : Ov;

    const __half* Ag = A  + (size_t)bm * 128 * 512;
    const __half* Bg = Bw + (size_t)bn * 128 * 512;

    GEMM_MAINLOOP

    const size_t cbase = (size_t)bm * 128 * 512 + (size_t)bn * 128;
    #pragma unroll
    for (int mt = 0; mt < 4; ++mt) {
        const int r0 = warpM * 64 + mt * 16 + gid;
        #pragma unroll
        for (int nt = 0; nt < 4; ++nt) {
            const int c0 = warpN * 32 + nt * 8 + tig * 2;
            size_t o = cbase + (size_t)r0 * 512 + c0;
            *(__half2*)(Co + o)           = __floats2half2_rn(acc[mt][nt][0], acc[mt][nt][1]);
            *(__half2*)(Co + o + 8 * 512) = __floats2half2_rn(acc[mt][nt][2], acc[mt][nt][3]);
        }
    }
}

// ---------------------------------------------------------------------------
// Output GEMM: A = g_ctx fp16, B = g_wo fp16, C = out fp32 + bias.
// ---------------------------------------------------------------------------
__global__ __launch_bounds__(256, 2)
void gemm_out_kernel(const __half* __restrict__ A, float* __restrict__ Cout,
                     const float* __restrict__ bias) {
    GEMM_CORE_DECLS
    const int bn = blockIdx.x;
    const int bm = blockIdx.y;

    const __half* Ag = A    + (size_t)bm * 128 * 512;
    const __half* Bg = g_wo + (size_t)bn * 128 * 512;

    GEMM_MAINLOOP

    const size_t cbase = (size_t)bm * 128 * 512 + (size_t)bn * 128;
    #pragma unroll
    for (int mt = 0; mt < 4; ++mt) {
        const int r0 = warpM * 64 + mt * 16 + gid;
        #pragma unroll
        for (int nt = 0; nt < 4; ++nt) {
            const int c0 = warpN * 32 + nt * 8 + tig * 2;
            const float b0 = bias[bn * 128 + c0];
            const float b1 = bias[bn * 128 + c0 + 1];
            size_t o = cbase + (size_t)r0 * 512 + c0;
            *(float2*)(Cout + o)           = make_float2(acc[mt][nt][0] + b0, acc[mt][nt][1] + b1);
            *(float2*)(Cout + o + 8 * 512) = make_float2(acc[mt][nt][2] + b0, acc[mt][nt][3] + b1);
        }
    }
}

// ---------------------------------------------------------------------------
// Fused attention middle (EXACT R11 config — measured best: occ 3, separate
// sSim buffer; R13's alias+occ4 variant was +16us).
// ---------------------------------------------------------------------------
__global__ __launch_bounds__(256, 3)
void attn_kernel(const float* __restrict__ mask,
                 const float* __restrict__ ln_g, const float* __restrict__ ln_b,
                 const float* __restrict__ beta) {
    constexpr int PADH = 520;   // fp16 row stride (halves)
    extern __shared__ char smraw[];
    float*  sSym = (float*)(smraw);                  // 256 f
    float*  sSim = (float*)(smraw + 1024);           // 2048 f
    __half* sQh  = (__half*)(smraw + 9216);          // 16*520 h
    __half* sKh  = (__half*)(smraw + 25856);         // 16*520 h
    __half* sMh  = (__half*)(smraw + 42496);         // 16*520 h (end 59136)

    const int tid  = threadIdx.x;
    const int warp = tid >> 5;
    const int lane = tid & 31;
    const int gid  = lane >> 2;
    const int tig  = lane & 3;
    const size_t base = (size_t)blockIdx.x * 8192;

    // async prefetch q,k (fp16) -> smem; overlaps LN + sym
    {
        const uint32_t sqb = smem_u32(sQh);
        const uint32_t skb = smem_u32(sKh);
        const __half* qg = g_q + base;
        const __half* kg = g_k + base;
        #pragma unroll
        for (int r = 0; r < 4; ++r) {
            int f = tid + 256 * r;
            int row = f >> 6, c8 = f & 63;
            uint32_t off = (uint32_t)(row * PADH + c8 * 8) * 2u;
            asm volatile("cp.async.ca.shared.global [%0], [%1], 16;"
                         :: "r"(sqb + off), "l"(qg + (size_t)row * 512 + c8 * 8));
            asm volatile("cp.async.ca.shared.global [%0], [%1], 16;"
                         :: "r"(skb + off), "l"(kg + (size_t)row * 512 + c8 * 8));
        }
        CP_COMMIT();
    }

    // layernorm(mask) -> sMh (fp16): warp per row, 2 rows/warp
    #pragma unroll
    for (int p = 0; p < 2; ++p) {
        const int r = warp + p * 8;
        const float4* mg = (const float4*)(mask + base + (size_t)r * 512);
        float4 vv[4];
        float s = 0.f, sq = 0.f;
        #pragma unroll
        for (int u = 0; u < 4; ++u) {
            vv[u] = mg[lane + 32 * u];
            s  += vv[u].x + vv[u].y + vv[u].z + vv[u].w;
            sq += vv[u].x * vv[u].x + vv[u].y * vv[u].y + vv[u].z * vv[u].z + vv[u].w * vv[u].w;
        }
        #pragma unroll
        for (int o = 16; o; o >>= 1) {
            s  += __shfl_xor_sync(0xffffffffu, s,  o);
            sq += __shfl_xor_sync(0xffffffffu, sq, o);
        }
        const float mu  = s * (1.f / 512.f);
        const float inv = rsqrtf(sq * (1.f / 512.f) - mu * mu + 1e-5f);
        const float4* gg = (const float4*)ln_g;
        const float4* bv = (const float4*)ln_b;
        uint2* mr = (uint2*)(sMh + r * PADH);
        #pragma unroll
        for (int u = 0; u < 4; ++u) {
            float4 g4 = gg[lane + 32 * u], b4 = bv[lane + 32 * u];
            float m0 = (vv[u].x - mu) * inv * g4.x + b4.x;
            float m1 = (vv[u].y - mu) * inv * g4.y + b4.y;
            float m2 = (vv[u].z - mu) * inv * g4.z + b4.z;
            float m3 = (vv[u].w - mu) * inv * g4.w + b4.w;
            mr[lane + 32 * u] = make_uint2(h2b(__floats2half2_rn(m0, m1)),
                                           h2b(__floats2half2_rn(m2, m3)));
        }
    }
    __syncthreads();

    // sym = (m m^T)/sqrt(C) via fp16 mma: warps 0,1
    if (warp < 2) {
        float acc4[4] = {0.f, 0.f, 0.f, 0.f};
        const int nb = warp * 8;
        #pragma unroll 4
        for (int k16 = 0; k16 < 32; ++k16) {
            const int kb = k16 * 16 + tig * 2;
            uint32_t aF[4], bF[2];
            aF[0] = *(const uint32_t*)(sMh + gid * PADH + kb);
            aF[1] = *(const uint32_t*)(sMh + (gid + 8) * PADH + kb);
            aF[2] = *(const uint32_t*)(sMh + gid * PADH + kb + 8);
            aF[3] = *(const uint32_t*)(sMh + (gid + 8) * PADH + kb + 8);
            bF[0] = *(const uint32_t*)(sMh + (nb + gid) * PADH + kb);
            bF[1] = *(const uint32_t*)(sMh + (nb + gid) * PADH + kb + 8);
            mma_f16(acc4, aF, bF);
        }
        const float S = 0.044194173824159216f;  // 1/sqrt(512)
        const int cc = nb + tig * 2;
        sSym[gid * 16 + cc]           = (gid == cc)         ? 0.f : acc4[0] * S;
        sSym[gid * 16 + cc + 1]       = (gid == cc + 1)     ? 0.f : acc4[1] * S;
        sSym[(gid + 8) * 16 + cc]     = (gid + 8 == cc)     ? 0.f : acc4[2] * S;
        sSym[(gid + 8) * 16 + cc + 1] = (gid + 8 == cc + 1) ? 0.f : acc4[3] * S;
    }
    asm volatile("cp.async.wait_group 0;" ::: "memory");
    __syncthreads();

    // sim[h] = q_h k_h^T /8 + sym*beta[h] via fp16 mma: warp h
    {
        const int hb = warp * 64;
        const float bh = beta[warp];
        float acc8[2][4];
        #pragma unroll
        for (int nt = 0; nt < 2; ++nt)
            #pragma unroll
            for (int r = 0; r < 4; ++r) acc8[nt][r] = 0.f;

        #pragma unroll
        for (int k16 = 0; k16 < 4; ++k16) {
            const int kb = hb + k16 * 16 + tig * 2;
            uint32_t aF[4], bF[2];
            aF[0] = *(const uint32_t*)(sQh + gid * PADH + kb);
            aF[1] = *(const uint32_t*)(sQh + (gid + 8) * PADH + kb);
            aF[2] = *(const uint32_t*)(sQh + gid * PADH + kb + 8);
            aF[3] = *(const uint32_t*)(sQh + (gid + 8) * PADH + kb + 8);
            #pragma unroll
            for (int nt = 0; nt < 2; ++nt) {
                bF[0] = *(const uint32_t*)(sKh + (nt * 8 + gid) * PADH + kb);
                bF[1] = *(const uint32_t*)(sKh + (nt * 8 + gid) * PADH + kb + 8);
                mma_f16(acc8[nt], aF, bF);
            }
        }
        float* simh = sSim + warp * 256;
        #pragma unroll
        for (int nt = 0; nt < 2; ++nt) {
            const int c0 = nt * 8 + tig * 2;
            simh[gid * 16 + c0]           = acc8[nt][0] * 0.125f + sSym[gid * 16 + c0] * bh;
            simh[gid * 16 + c0 + 1]       = acc8[nt][1] * 0.125f + sSym[gid * 16 + c0 + 1] * bh;
            simh[(gid + 8) * 16 + c0]     = acc8[nt][2] * 0.125f + sSym[(gid + 8) * 16 + c0] * bh;
            simh[(gid + 8) * 16 + c0 + 1] = acc8[nt][3] * 0.125f + sSym[(gid + 8) * 16 + c0 + 1] * bh;
        }
    }
    __syncthreads();

    // softmax over j: one thread per (h,i) row
    if (tid < 128) {
        float* row = sSim + tid * 16;
        float mx = row[0];
        #pragma unroll
        for (int j = 1; j < 16; ++j) mx = fmaxf(mx, row[j]);
        float s = 0.f;
        #pragma unroll
        for (int j = 0; j < 16; ++j) { float e = __expf(row[j] - mx); row[j] = e; s += e; }
        const float inv = 1.f / s;
        #pragma unroll
        for (int j = 0; j < 16; ++j) row[j] *= inv;
    }
    __syncthreads();

    // ctx = attn @ v : thread owns 2 adjacent cols
    {
        const __half2* vg2 = (const __half2*)(g_v + base);
        float2 vr[16];
        #pragma unroll
        for (int j = 0; j < 16; ++j) vr[j] = __half22float2(vg2[j * 256 + tid]);
        const float* ab = sSim + warp * 256;
        __half2* cg2 = (__half2*)(g_ctx + base);
        #pragma unroll
        for (int i = 0; i < 16; ++i) {
            const float* ar = ab + i * 16;
            float a0 = 0.f, a1 = 0.f;
            #pragma unroll
            for (int j = 0; j < 16; ++j) {
                const float a = ar[j];
                a0 += a * vr[j].x;
                a1 += a * vr[j].y;
            }
            cg2[i * 256 + tid] = __floats2half2_rn(a0, a1);
        }
    }
}

// ---------------------------------------------------------------------------
// Launch
// ---------------------------------------------------------------------------
extern "C" void kernel_launch(void* const* d_in, const int* in_sizes, int n_in,
                              void* d_out, int out_size) {
    const float* x    = (const float*)d_in[0];
    const float* mask = (const float*)d_in[1];
    const float* w_q  = (const float*)d_in[2];
    const float* w_k  = (const float*)d_in[3];
    const float* w_v  = (const float*)d_in[4];
    const float* w_o  = (const float*)d_in[5];
    const float* b_o  = (const float*)d_in[6];
    const float* beta = (const float*)d_in[7];
    const float* ln_g = (const float*)d_in[8];
    const float* ln_b = (const float*)d_in[9];
    float* out = (float*)d_out;

    __half *xh, *wq, *wk, *wv, *wo, *q, *k, *v, *ctx;
    cudaGetSymbolAddress((void**)&xh,  g_xh);
    cudaGetSymbolAddress((void**)&wq,  g_wq);
    cudaGetSymbolAddress((void**)&wk,  g_wk);
    cudaGetSymbolAddress((void**)&wv,  g_wv);
    cudaGetSymbolAddress((void**)&wo,  g_wo);
    cudaGetSymbolAddress((void**)&q,   g_q);
    cudaGetSymbolAddress((void**)&k,   g_k);
    cudaGetSymbolAddress((void**)&v,   g_v);
    cudaGetSymbolAddress((void**)&ctx, g_ctx);

    const int bt = in_sizes[0] / C_DIM;       // B*T = 131072
    const int bb = bt / 16;                   // B   = 8192

    const int gemm_smem = 61440;
    const int attn_smem = 59136;
    cudaFuncSetAttribute(gemm_qkv_kernel, cudaFuncAttributeMaxDynamicSharedMemorySize, gemm_smem);
    cudaFuncSetAttribute(gemm_out_kernel, cudaFuncAttributeMaxDynamicSharedMemorySize, gemm_smem);
    cudaFuncSetAttribute(attn_kernel,     cudaFuncAttributeMaxDynamicSharedMemorySize, attn_smem);

    // fp32 -> fp16 converts: x (one launch) + all 4 weights (one launch)
    const int n4x = bt * 128;                 // x float4 count
    cvt_kernel<<<(n4x + 255) / 256, 256>>>((const float4*)x, (uint2*)xh, n4x);
    cvt4_kernel<<<1024, 256>>>((const float4*)w_q, (const float4*)w_k,
                               (const float4*)w_v, (const float4*)w_o,
                               (uint2*)wq, (uint2*)wk, (uint2*)wv, (uint2*)wo);

    dim3 grid_qkv(12, bt / 128);
    dim3 grid_out(4,  bt / 128);
    gemm_qkv_kernel<<<grid_qkv, 256, gemm_smem>>>(xh, q, k, v);
    attn_kernel<<<bb, 256, attn_smem>>>(mask, ln_g, ln_b, beta);
    gemm_out_kernel<<<grid_out, 256, gemm_smem>>>(ctx, out, b_o);
}

// round 16
// speedup vs baseline: 1.3398x; 1.1255x over previous
#include <cuda_runtime.h>
#include <cuda_fp16.h>
#include <cstdint>
#include <cstddef>

// Problem shape (fixed by the dataset): B=8192, T=16, C=512, H=8, DH=64
#define BT_TOTAL 131072          // B*T
#define C_DIM    512

// ---------------------------------------------------------------------------
// Scratch (device globals; no allocations allowed). All fp16.
// ---------------------------------------------------------------------------
__device__ __half g_xh[BT_TOTAL * C_DIM];    // x converted to fp16
__device__ __half g_wq[C_DIM * C_DIM];
__device__ __half g_wk[C_DIM * C_DIM];
__device__ __half g_wv[C_DIM * C_DIM];
__device__ __half g_wo[C_DIM * C_DIM];
__device__ __half g_q[BT_TOTAL * C_DIM];
__device__ __half g_k[BT_TOTAL * C_DIM];
__device__ __half g_v[BT_TOTAL * C_DIM];
__device__ __half g_ctx[BT_TOTAL * C_DIM];

// ---------------------------------------------------------------------------
// Helpers
// ---------------------------------------------------------------------------
__device__ __forceinline__ uint32_t smem_u32(const void* p) {
    uint32_t a;
    asm("{ .reg .u64 t; cvta.to.shared.u64 t, %1; cvt.u32.u64 %0, t; }" : "=r"(a) : "l"(p));
    return a;
}
__device__ __forceinline__ uint32_t h2b(__half2 h) {
    return *reinterpret_cast<uint32_t*>(&h);
}
__device__ __forceinline__ void mma_f16(float* d, const uint32_t* a, const uint32_t* b) {
    asm volatile(
        "mma.sync.aligned.m16n8k16.row.col.f32.f16.f16.f32 "
        "{%0,%1,%2,%3}, {%4,%5,%6,%7}, {%8,%9}, {%0,%1,%2,%3};\n"
        : "+f"(d[0]), "+f"(d[1]), "+f"(d[2]), "+f"(d[3])
        : "r"(a[0]), "r"(a[1]), "r"(a[2]), "r"(a[3]),
          "r"(b[0]), "r"(b[1]));
}
#define LDSM4(r0, r1, r2, r3, addr)                                            \
    asm volatile("ldmatrix.sync.aligned.m8n8.x4.shared.b16 {%0,%1,%2,%3}, [%4];" \
        : "=r"(r0), "=r"(r1), "=r"(r2), "=r"(r3) : "r"(addr))
#define CP_ASYNC16(dst, src)                                                   \
    asm volatile("cp.async.cg.shared.global [%0], [%1], 16;" :: "r"(dst), "l"(src))
#define CP_COMMIT()  asm volatile("cp.async.commit_group;" ::: "memory")
#define CP_WAIT(n)   asm volatile("cp.async.wait_group %0;" :: "n"(n) : "memory")

// ---------------------------------------------------------------------------
// fp32 -> fp16 bulk convert: x (big, own launch)
// ---------------------------------------------------------------------------
__global__ __launch_bounds__(256)
void cvt_kernel(const float4* __restrict__ src, uint2* __restrict__ dst, int n4) {
    int i = blockIdx.x * 256 + threadIdx.x;
    if (i < n4) {
        float4 v = src[i];
        dst[i] = make_uint2(h2b(__floats2half2_rn(v.x, v.y)),
                            h2b(__floats2half2_rn(v.z, v.w)));
    }
}

// All 4 weight matrices in ONE launch (grid 1024; 256 blocks per matrix).
__global__ __launch_bounds__(256)
void cvt4_kernel(const float4* __restrict__ s0, const float4* __restrict__ s1,
                 const float4* __restrict__ s2, const float4* __restrict__ s3,
                 uint2* __restrict__ d0, uint2* __restrict__ d1,
                 uint2* __restrict__ d2, uint2* __restrict__ d3) {
    const int m = blockIdx.x >> 8;                    // 0..3
    const int i = (blockIdx.x & 255) * 256 + threadIdx.x;  // 0..65535
    const float4* s = (m == 0) ? s0 : (m == 1) ? s1 : (m == 2) ? s2 : s3;
    uint2*       d = (m == 0) ? d0 : (m == 1) ? d1 : (m == 2) ? d2 : d3;
    float4 v = s[i];
    d[i] = make_uint2(h2b(__floats2half2_rn(v.x, v.y)),
                      h2b(__floats2half2_rn(v.z, v.w)));
}

// ===========================================================================
// fp16 GEMM core: tile 128x128x64, 256 threads, K-chunk 64 (8 k-iterations).
// Keeps the verified R11 structure: 2 CTAs/SM, TWO barriers per iteration,
// same per-warp fragment/mma pattern (4 ks-slices of k16 instead of 2).
// Only delta vs R11: 16 barriers/CTA instead of 32, longer compute runs.
// 2-stage ring, depth-1 prefetch (stages are 2x bigger, same lead time).
// smem: stage s @ s*36864: A (128 x 144B), B @ +18432 (128 x 144B).
// Total 73728 B -> 2 CTAs/SM. Row stride 144B: LDSM phase banks
// (9r+c) mod 8 = (r+c) mod 8, distinct per 8-row phase.
// ===========================================================================
#define GEMM_CORE_DECLS                                                        \
    extern __shared__ char smraw[];                                            \
    const uint32_t sbase = smem_u32(smraw);                                    \
    const int tid   = threadIdx.x;                                             \
    const int lane  = tid & 31;                                                \
    const int warp  = tid >> 5;                                                \
    const int warpM = warp >> 2;                                               \
    const int warpN = warp & 3;                                                \
    const int gid   = lane >> 2;                                               \
    const int tig   = lane & 3;                                                \
    const uint32_t aOff = (uint32_t)((warpM * 64 + (lane & 15)) * 144 + (lane >> 4) * 16); \
    const uint32_t bOff = (uint32_t)((warpN * 32 + (lane >> 4) * 8 + (lane & 7)) * 144     \
                                     + ((lane >> 3) & 1) * 16);                \
    float acc[4][4][4];                                                        \
    _Pragma("unroll")                                                          \
    for (int i = 0; i < 4; ++i)                                                \
        _Pragma("unroll")                                                      \
        for (int j = 0; j < 4; ++j)                                            \
            _Pragma("unroll")                                                  \
            for (int r = 0; r < 4; ++r) acc[i][j][r] = 0.f;

#define GEMM_ISSUE(kt)                                                         \
    {                                                                          \
        const int s_ = (kt) & 1;                                               \
        const uint32_t da_ = sbase + s_ * 36864;                               \
        const uint32_t db_ = da_ + 18432;                                      \
        const __half* ag_ = Ag + (kt) * 64;                                    \
        const __half* bg_ = Bg + (kt) * 64;                                    \
        _Pragma("unroll")                                                      \
        for (int i_ = 0; i_ < 4; ++i_) {                                       \
            const int idx_ = tid + i_ * 256;                                   \
            const int row_ = idx_ >> 3, c_ = idx_ & 7;                         \
            CP_ASYNC16(da_ + (uint32_t)(row_ * 144 + c_ * 16),                 \
                       ag_ + (size_t)row_ * 512 + c_ * 8);                     \
            CP_ASYNC16(db_ + (uint32_t)(row_ * 144 + c_ * 16),                 \
                       bg_ + (size_t)row_ * 512 + c_ * 8);                     \
        }                                                                      \
        CP_COMMIT();                                                           \
    }

#define GEMM_COMPUTE(s)                                                        \
    {                                                                          \
        const uint32_t sa_ = sbase + (s) * 36864 + aOff;                       \
        const uint32_t sb_ = sbase + (s) * 36864 + 18432 + bOff;               \
        _Pragma("unroll")                                                      \
        for (int ks = 0; ks < 4; ++ks) {                                       \
            uint32_t aF[4][4], bF[8];                                          \
            _Pragma("unroll")                                                  \
            for (int mt = 0; mt < 4; ++mt)                                     \
                LDSM4(aF[mt][0], aF[mt][1], aF[mt][2], aF[mt][3],              \
                      sa_ + mt * 2304 + ks * 32);                              \
            _Pragma("unroll")                                                  \
            for (int p = 0; p < 2; ++p)                                        \
                LDSM4(bF[p*4], bF[p*4+1], bF[p*4+2], bF[p*4+3],                \
                      sb_ + p * 2304 + ks * 32);                               \
            _Pragma("unroll")                                                  \
            for (int mt = 0; mt < 4; ++mt)                                     \
                _Pragma("unroll")                                              \
                for (int nt = 0; nt < 4; ++nt)                                 \
                    mma_f16(acc[mt][nt], aF[mt], &bF[nt * 2]);                 \
        }                                                                      \
    }

#define GEMM_MAINLOOP                                                          \
    GEMM_ISSUE(0)                                                              \
    _Pragma("unroll 1")                                                        \
    for (int kt = 0; kt < 8; ++kt) {                                           \
        if (kt + 1 < 8) { GEMM_ISSUE(kt + 1) } else { CP_COMMIT(); }           \
        CP_WAIT(1);                                                            \
        __syncthreads();                                                       \
        GEMM_COMPUTE(kt & 1)                                                   \
        __syncthreads();                                                       \
    }

// ---------------------------------------------------------------------------
// Merged QKV GEMM: grid (12, M/128). blockIdx.x>>2 selects {q,k,v}.
// ---------------------------------------------------------------------------
__global__ __launch_bounds__(256, 2)
void gemm_qkv_kernel(const __half* __restrict__ A,
                     __half* __restrict__ Oq, __half* __restrict__ Ok,
                     __half* __restrict__ Ov) {
    GEMM_CORE_DECLS
    const int sel = blockIdx.x >> 2;
    const int bn  = blockIdx.x & 3;
    const int bm  = blockIdx.y;

    const __half* Bw = (sel == 0) ? g_wq : (sel == 1) ? g_wk : g_wv;
    __half*       Co = (sel == 0) ? Oq   : (sel == 1) ? Ok   : Ov;

    const __half* Ag = A  + (size_t)bm * 128 * 512;
    const __half* Bg = Bw + (size_t)bn * 128 * 512;

    GEMM_MAINLOOP

    const size_t cbase = (size_t)bm * 128 * 512 + (size_t)bn * 128;
    #pragma unroll
    for (int mt = 0; mt < 4; ++mt) {
        const int r0 = warpM * 64 + mt * 16 + gid;
        #pragma unroll
        for (int nt = 0; nt < 4; ++nt) {
            const int c0 = warpN * 32 + nt * 8 + tig * 2;
            size_t o = cbase + (size_t)r0 * 512 + c0;
            *(__half2*)(Co + o)           = __floats2half2_rn(acc[mt][nt][0], acc[mt][nt][1]);
            *(__half2*)(Co + o + 8 * 512) = __floats2half2_rn(acc[mt][nt][2], acc[mt][nt][3]);
        }
    }
}

// ---------------------------------------------------------------------------
// Output GEMM: A = g_ctx fp16, B = g_wo fp16, C = out fp32 + bias.
// ---------------------------------------------------------------------------
__global__ __launch_bounds__(256, 2)
void gemm_out_kernel(const __half* __restrict__ A, float* __restrict__ Cout,
                     const float* __restrict__ bias) {
    GEMM_CORE_DECLS
    const int bn = blockIdx.x;
    const int bm = blockIdx.y;

    const __half* Ag = A    + (size_t)bm * 128 * 512;
    const __half* Bg = g_wo + (size_t)bn * 128 * 512;

    GEMM_MAINLOOP

    const size_t cbase = (size_t)bm * 128 * 512 + (size_t)bn * 128;
    #pragma unroll
    for (int mt = 0; mt < 4; ++mt) {
        const int r0 = warpM * 64 + mt * 16 + gid;
        #pragma unroll
        for (int nt = 0; nt < 4; ++nt) {
            const int c0 = warpN * 32 + nt * 8 + tig * 2;
            const float b0 = bias[bn * 128 + c0];
            const float b1 = bias[bn * 128 + c0 + 1];
            size_t o = cbase + (size_t)r0 * 512 + c0;
            *(float2*)(Cout + o)           = make_float2(acc[mt][nt][0] + b0, acc[mt][nt][1] + b1);
            *(float2*)(Cout + o + 8 * 512) = make_float2(acc[mt][nt][2] + b0, acc[mt][nt][3] + b1);
        }
    }
}

// ---------------------------------------------------------------------------
// Fused attention middle (EXACT R11/R15 config — measured best).
// ---------------------------------------------------------------------------
__global__ __launch_bounds__(256, 3)
void attn_kernel(const float* __restrict__ mask,
                 const float* __restrict__ ln_g, const float* __restrict__ ln_b,
                 const float* __restrict__ beta) {
    constexpr int PADH = 520;   // fp16 row stride (halves)
    extern __shared__ char smraw[];
    float*  sSym = (float*)(smraw);                  // 256 f
    float*  sSim = (float*)(smraw + 1024);           // 2048 f
    __half* sQh  = (__half*)(smraw + 9216);          // 16*520 h
    __half* sKh  = (__half*)(smraw + 25856);         // 16*520 h
    __half* sMh  = (__half*)(smraw + 42496);         // 16*520 h (end 59136)

    const int tid  = threadIdx.x;
    const int warp = tid >> 5;
    const int lane = tid & 31;
    const int gid  = lane >> 2;
    const int tig  = lane & 3;
    const size_t base = (size_t)blockIdx.x * 8192;

    // async prefetch q,k (fp16) -> smem; overlaps LN + sym
    {
        const uint32_t sqb = smem_u32(sQh);
        const uint32_t skb = smem_u32(sKh);
        const __half* qg = g_q + base;
        const __half* kg = g_k + base;
        #pragma unroll
        for (int r = 0; r < 4; ++r) {
            int f = tid + 256 * r;
            int row = f >> 6, c8 = f & 63;
            uint32_t off = (uint32_t)(row * PADH + c8 * 8) * 2u;
            asm volatile("cp.async.ca.shared.global [%0], [%1], 16;"
                         :: "r"(sqb + off), "l"(qg + (size_t)row * 512 + c8 * 8));
            asm volatile("cp.async.ca.shared.global [%0], [%1], 16;"
                         :: "r"(skb + off), "l"(kg + (size_t)row * 512 + c8 * 8));
        }
        CP_COMMIT();
    }

    // layernorm(mask) -> sMh (fp16): warp per row, 2 rows/warp
    #pragma unroll
    for (int p = 0; p < 2; ++p) {
        const int r = warp + p * 8;
        const float4* mg = (const float4*)(mask + base + (size_t)r * 512);
        float4 vv[4];
        float s = 0.f, sq = 0.f;
        #pragma unroll
        for (int u = 0; u < 4; ++u) {
            vv[u] = mg[lane + 32 * u];
            s  += vv[u].x + vv[u].y + vv[u].z + vv[u].w;
            sq += vv[u].x * vv[u].x + vv[u].y * vv[u].y + vv[u].z * vv[u].z + vv[u].w * vv[u].w;
        }
        #pragma unroll
        for (int o = 16; o; o >>= 1) {
            s  += __shfl_xor_sync(0xffffffffu, s,  o);
            sq += __shfl_xor_sync(0xffffffffu, sq, o);
        }
        const float mu  = s * (1.f / 512.f);
        const float inv = rsqrtf(sq * (1.f / 512.f) - mu * mu + 1e-5f);
        const float4* gg = (const float4*)ln_g;
        const float4* bv = (const float4*)ln_b;
        uint2* mr = (uint2*)(sMh + r * PADH);
        #pragma unroll
        for (int u = 0; u < 4; ++u) {
            float4 g4 = gg[lane + 32 * u], b4 = bv[lane + 32 * u];
            float m0 = (vv[u].x - mu) * inv * g4.x + b4.x;
            float m1 = (vv[u].y - mu) * inv * g4.y + b4.y;
            float m2 = (vv[u].z - mu) * inv * g4.z + b4.z;
            float m3 = (vv[u].w - mu) * inv * g4.w + b4.w;
            mr[lane + 32 * u] = make_uint2(h2b(__floats2half2_rn(m0, m1)),
                                           h2b(__floats2half2_rn(m2, m3)));
        }
    }
    __syncthreads();

    // sym = (m m^T)/sqrt(C) via fp16 mma: warps 0,1
    if (warp < 2) {
        float acc4[4] = {0.f, 0.f, 0.f, 0.f};
        const int nb = warp * 8;
        #pragma unroll 4
        for (int k16 = 0; k16 < 32; ++k16) {
            const int kb = k16 * 16 + tig * 2;
            uint32_t aF[4], bF[2];
            aF[0] = *(const uint32_t*)(sMh + gid * PADH + kb);
            aF[1] = *(const uint32_t*)(sMh + (gid + 8) * PADH + kb);
            aF[2] = *(const uint32_t*)(sMh + gid * PADH + kb + 8);
            aF[3] = *(const uint32_t*)(sMh + (gid + 8) * PADH + kb + 8);
            bF[0] = *(const uint32_t*)(sMh + (nb + gid) * PADH + kb);
            bF[1] = *(const uint32_t*)(sMh + (nb + gid) * PADH + kb + 8);
            mma_f16(acc4, aF, bF);
        }
        const float S = 0.044194173824159216f;  // 1/sqrt(512)
        const int cc = nb + tig * 2;
        sSym[gid * 16 + cc]           = (gid == cc)         ? 0.f : acc4[0] * S;
        sSym[gid * 16 + cc + 1]       = (gid == cc + 1)     ? 0.f : acc4[1] * S;
        sSym[(gid + 8) * 16 + cc]     = (gid + 8 == cc)     ? 0.f : acc4[2] * S;
        sSym[(gid + 8) * 16 + cc + 1] = (gid + 8 == cc + 1) ? 0.f : acc4[3] * S;
    }
    asm volatile("cp.async.wait_group 0;" ::: "memory");
    __syncthreads();

    // sim[h] = q_h k_h^T /8 + sym*beta[h] via fp16 mma: warp h
    {
        const int hb = warp * 64;
        const float bh = beta[warp];
        float acc8[2][4];
        #pragma unroll
        for (int nt = 0; nt < 2; ++nt)
            #pragma unroll
            for (int r = 0; r < 4; ++r) acc8[nt][r] = 0.f;

        #pragma unroll
        for (int k16 = 0; k16 < 4; ++k16) {
            const int kb = hb + k16 * 16 + tig * 2;
            uint32_t aF[4], bF[2];
            aF[0] = *(const uint32_t*)(sQh + gid * PADH + kb);
            aF[1] = *(const uint32_t*)(sQh + (gid + 8) * PADH + kb);
            aF[2] = *(const uint32_t*)(sQh + gid * PADH + kb + 8);
            aF[3] = *(const uint32_t*)(sQh + (gid + 8) * PADH + kb + 8);
            #pragma unroll
            for (int nt = 0; nt < 2; ++nt) {
                bF[0] = *(const uint32_t*)(sKh + (nt * 8 + gid) * PADH + kb);
                bF[1] = *(const uint32_t*)(sKh + (nt * 8 + gid) * PADH + kb + 8);
                mma_f16(acc8[nt], aF, bF);
            }
        }
        float* simh = sSim + warp * 256;
        #pragma unroll
        for (int nt = 0; nt < 2; ++nt) {
            const int c0 = nt * 8 + tig * 2;
            simh[gid * 16 + c0]           = acc8[nt][0] * 0.125f + sSym[gid * 16 + c0] * bh;
            simh[gid * 16 + c0 + 1]       = acc8[nt][1] * 0.125f + sSym[gid * 16 + c0 + 1] * bh;
            simh[(gid + 8) * 16 + c0]     = acc8[nt][2] * 0.125f + sSym[(gid + 8) * 16 + c0] * bh;
            simh[(gid + 8) * 16 + c0 + 1] = acc8[nt][3] * 0.125f + sSym[(gid + 8) * 16 + c0 + 1] * bh;
        }
    }
    __syncthreads();

    // softmax over j: one thread per (h,i) row
    if (tid < 128) {
        float* row = sSim + tid * 16;
        float mx = row[0];
        #pragma unroll
        for (int j = 1; j < 16; ++j) mx = fmaxf(mx, row[j]);
        float s = 0.f;
        #pragma unroll
        for (int j = 0; j < 16; ++j) { float e = __expf(row[j] - mx); row[j] = e; s += e; }
        const float inv = 1.f / s;
        #pragma unroll
        for (int j = 0; j < 16; ++j) row[j] *= inv;
    }
    __syncthreads();

    // ctx = attn @ v : thread owns 2 adjacent cols
    {
        const __half2* vg2 = (const __half2*)(g_v + base);
        float2 vr[16];
        #pragma unroll
        for (int j = 0; j < 16; ++j) vr[j] = __half22float2(vg2[j * 256 + tid]);
        const float* ab = sSim + warp * 256;
        __half2* cg2 = (__half2*)(g_ctx + base);
        #pragma unroll
        for (int i = 0; i < 16; ++i) {
            const float* ar = ab + i * 16;
            float a0 = 0.f, a1 = 0.f;
            #pragma unroll
            for (int j = 0; j < 16; ++j) {
                const float a = ar[j];
                a0 += a * vr[j].x;
                a1 += a * vr[j].y;
            }
            cg2[i * 256 + tid] = __floats2half2_rn(a0, a1);
        }
    }
}

// ---------------------------------------------------------------------------
// Launch
// ---------------------------------------------------------------------------
extern "C" void kernel_launch(void* const* d_in, const int* in_sizes, int n_in,
                              void* d_out, int out_size) {
    const float* x    = (const float*)d_in[0];
    const float* mask = (const float*)d_in[1];
    const float* w_q  = (const float*)d_in[2];
    const float* w_k  = (const float*)d_in[3];
    const float* w_v  = (const float*)d_in[4];
    const float* w_o  = (const float*)d_in[5];
    const float* b_o  = (const float*)d_in[6];
    const float* beta = (const float*)d_in[7];
    const float* ln_g = (const float*)d_in[8];
    const float* ln_b = (const float*)d_in[9];
    float* out = (float*)d_out;

    __half *xh, *wq, *wk, *wv, *wo, *q, *k, *v, *ctx;
    cudaGetSymbolAddress((void**)&xh,  g_xh);
    cudaGetSymbolAddress((void**)&wq,  g_wq);
    cudaGetSymbolAddress((void**)&wk,  g_wk);
    cudaGetSymbolAddress((void**)&wv,  g_wv);
    cudaGetSymbolAddress((void**)&wo,  g_wo);
    cudaGetSymbolAddress((void**)&q,   g_q);
    cudaGetSymbolAddress((void**)&k,   g_k);
    cudaGetSymbolAddress((void**)&v,   g_v);
    cudaGetSymbolAddress((void**)&ctx, g_ctx);

    const int bt = in_sizes[0] / C_DIM;       // B*T = 131072
    const int bb = bt / 16;                   // B   = 8192

    const int gemm_smem = 73728;
    const int attn_smem = 59136;
    cudaFuncSetAttribute(gemm_qkv_kernel, cudaFuncAttributeMaxDynamicSharedMemorySize, gemm_smem);
    cudaFuncSetAttribute(gemm_out_kernel, cudaFuncAttributeMaxDynamicSharedMemorySize, gemm_smem);
    cudaFuncSetAttribute(attn_kernel,     cudaFuncAttributeMaxDynamicSharedMemorySize, attn_smem);

    // fp32 -> fp16 converts: x (one launch) + all 4 weights (one launch)
    const int n4x = bt * 128;                 // x float4 count
    cvt_kernel<<<(n4x + 255) / 256, 256>>>((const float4*)x, (uint2*)xh, n4x);
    cvt4_kernel<<<1024, 256>>>((const float4*)w_q, (const float4*)w_k,
                               (const float4*)w_v, (const float4*)w_o,
                               (uint2*)wq, (uint2*)wk, (uint2*)wv, (uint2*)wo);

    dim3 grid_qkv(12, bt / 128);
    dim3 grid_out(4,  bt / 128);
    gemm_qkv_kernel<<<grid_qkv, 256, gemm_smem>>>(xh, q, k, v);
    attn_kernel<<<bb, 256, attn_smem>>>(mask, ln_g, ln_b, beta);
    gemm_out_kernel<<<grid_out, 256, gemm_smem>>>(ctx, out, b_o);
}